// round 1
// baseline (speedup 1.0000x reference)
#include <cuda_runtime.h>
#include <math.h>

// Problem constants (fixed by the dataset)
#define NE 4096
#define NW 8192
#define KD 128
#define GG 1024
#define MM 64
#define JJ 256

#define NBLK 1024   // blocks for the big reduce
#define NTHR 256    // threads for the big reduce

// Scratch (device globals — no runtime allocation allowed)
__device__ float g_Wt[NW * KD];          // transposed W: Wt[n*KD + k] = W[k*NW + n]  (4 MB)
__device__ float g_pr[NBLK];             // per-block partials: recon
__device__ float g_pw[NBLK];             // relu(W)^2
__device__ float g_pe[NBLK];             // relu(E)^2
__device__ float g_sim[GG];              // per-group word sim term
__device__ float g_ent[2];               // [0]=sum de^2, [1]=sum Se row gather

__device__ __forceinline__ float block_reduce(float v) {
    __shared__ float sh[32];
    int lane = threadIdx.x & 31;
    int wid  = threadIdx.x >> 5;
    #pragma unroll
    for (int o = 16; o > 0; o >>= 1) v += __shfl_down_sync(0xffffffffu, v, o);
    __syncthreads();                 // protect sh across repeated calls
    if (lane == 0) sh[wid] = v;
    __syncthreads();
    int nwarps = (blockDim.x + 31) >> 5;
    v = (threadIdx.x < nwarps) ? sh[threadIdx.x] : 0.0f;
    if (wid == 0) {
        #pragma unroll
        for (int o = 16; o > 0; o >>= 1) v += __shfl_down_sync(0xffffffffu, v, o);
    }
    return v;   // valid in thread 0
}

// ---------------------------------------------------------------------------
// 1) Transpose W (KD x NW) -> g_Wt (NW x KD), tiled via shared memory
// ---------------------------------------------------------------------------
__global__ void transpose_k(const float* __restrict__ W) {
    __shared__ float tile[32][33];
    int n = blockIdx.x * 32 + threadIdx.x;      // column of W (0..NW)
    int k = blockIdx.y * 32 + threadIdx.y;      // row of W    (0..KD)
    #pragma unroll
    for (int i = 0; i < 32; i += 8)
        tile[threadIdx.y + i][threadIdx.x] = W[(size_t)(k + i) * NW + n];
    __syncthreads();
    int ko = blockIdx.y * 32 + threadIdx.x;     // k (contiguous in Wt row? no: Wt row = n)
    int no = blockIdx.x * 32 + threadIdx.y;     // n
    #pragma unroll
    for (int i = 0; i < 32; i += 8)
        g_Wt[(size_t)(no + i) * KD + ko] = tile[threadIdx.x][threadIdx.y + i];
}

// ---------------------------------------------------------------------------
// 2) Big HBM-bound reduce: sum (a-p)^2 ; sum relu(W)^2 ; sum relu(E)^2
// ---------------------------------------------------------------------------
__global__ void big_reduce_k(const float* __restrict__ a,
                             const float* __restrict__ p,
                             const float* __restrict__ W,
                             const float* __restrict__ E) {
    const int tid    = blockIdx.x * blockDim.x + threadIdx.x;
    const int stride = gridDim.x * blockDim.x;

    float s_r = 0.0f, s_w = 0.0f, s_e = 0.0f;

    const float4* a4 = (const float4*)a;
    const float4* p4 = (const float4*)p;
    const int n4 = (NE * NW) / 4;     // 8M
    for (int i = tid; i < n4; i += stride) {
        float4 av = a4[i];
        float4 pv = p4[i];
        float d0 = av.x - pv.x, d1 = av.y - pv.y;
        float d2 = av.z - pv.z, d3 = av.w - pv.w;
        s_r += d0 * d0 + d1 * d1 + d2 * d2 + d3 * d3;
    }

    const float4* w4 = (const float4*)W;
    const int nw4 = (KD * NW) / 4;    // 256K
    for (int i = tid; i < nw4; i += stride) {
        float4 v = w4[i];
        float r0 = fmaxf(v.x, 0.f), r1 = fmaxf(v.y, 0.f);
        float r2 = fmaxf(v.z, 0.f), r3 = fmaxf(v.w, 0.f);
        s_w += r0 * r0 + r1 * r1 + r2 * r2 + r3 * r3;
    }

    const float4* e4 = (const float4*)E;
    const int ne4 = (NE * KD) / 4;    // 128K
    for (int i = tid; i < ne4; i += stride) {
        float4 v = e4[i];
        float r0 = fmaxf(v.x, 0.f), r1 = fmaxf(v.y, 0.f);
        float r2 = fmaxf(v.z, 0.f), r3 = fmaxf(v.w, 0.f);
        s_e += r0 * r0 + r1 * r1 + r2 * r2 + r3 * r3;
    }

    float br = block_reduce(s_r);
    float bw = block_reduce(s_w);
    float be = block_reduce(s_e);
    if (threadIdx.x == 0) {
        g_pr[blockIdx.x] = br;
        g_pw[blockIdx.x] = bw;
        g_pe[blockIdx.x] = be;
    }
}

// ---------------------------------------------------------------------------
// 3) Word-gather kernel: one block per g (128 threads = K dim)
//    diff_w[g] = sqrt( sum_{k,m} (Wt[sj[g]][k] - Wt[wi[g,m]][k])^2 )
//    sim[g]    = diff_w[g] * sum_m Sw[sj[g], wi[g,m]]
// ---------------------------------------------------------------------------
__global__ void gather_k(const float* __restrict__ Sw,
                         const int*   __restrict__ wi,
                         const int*   __restrict__ sj) {
    const int g = blockIdx.x;
    const int k = threadIdx.x;            // 0..127

    __shared__ int idxs[MM];
    const int j = sj[g];
    if (k < MM) idxs[k] = wi[g * MM + k];
    __syncthreads();

    const float wjk = g_Wt[(size_t)j * KD + k];

    float acc = 0.0f;
    #pragma unroll 4
    for (int m = 0; m < MM; m++) {
        float d = wjk - g_Wt[(size_t)idxs[m] * KD + k];
        acc += d * d;
    }

    float swv = 0.0f;
    if (k < MM) swv = Sw[(size_t)j * NW + idxs[k]];

    float d2 = block_reduce(acc);
    __syncthreads();
    float sw = block_reduce(swv);
    if (k == 0) g_sim[g] = sqrtf(d2) * sw;
}

// ---------------------------------------------------------------------------
// 4) Entity kernel: 1 block x 1024 threads
// ---------------------------------------------------------------------------
__global__ void entity_k(const float* __restrict__ E,
                         const float* __restrict__ Se,
                         const int*   __restrict__ ej,
                         const int*   __restrict__ row_ind_p) {
    const int row = row_ind_p[0];
    const int t = threadIdx.x;

    __shared__ float erow[KD];
    __shared__ int   ejs[JJ];
    if (t < KD) erow[t] = E[(size_t)row * KD + t];
    if (t < JJ) ejs[t] = ej[t];
    __syncthreads();

    float s_de = 0.0f;
    #pragma unroll 4
    for (int i = t; i < JJ * KD; i += 1024) {
        int jj = i >> 7;        // / KD
        int kk = i & (KD - 1);
        float d = erow[kk] - E[(size_t)ejs[jj] * KD + kk];
        s_de += d * d;
    }

    float s_se = 0.0f;
    if (t < JJ) s_se = Se[(size_t)row * NE + ejs[t]];

    float de = block_reduce(s_de);
    __syncthreads();
    float se = block_reduce(s_se);
    if (t == 0) { g_ent[0] = de; g_ent[1] = se; }
}

// ---------------------------------------------------------------------------
// 5) Final compose: reduce partials, emit scalar
// ---------------------------------------------------------------------------
__global__ void final_k(const float* __restrict__ lamb, float* __restrict__ out) {
    const int t = threadIdx.x;
    float sr = 0.f, sw = 0.f, se = 0.f, sim = 0.f;
    for (int i = t; i < NBLK; i += 256) {
        sr  += g_pr[i];
        sw  += g_pw[i];
        se  += g_pe[i];
    }
    for (int i = t; i < GG; i += 256) sim += g_sim[i];

    float Sr  = block_reduce(sr);   __syncthreads();
    float Sw_ = block_reduce(sw);   __syncthreads();
    float Se_ = block_reduce(se);   __syncthreads();
    float Sim = block_reduce(sim);

    if (t == 0) {
        float recon = sqrtf(Sr);
        float param = sqrtf(Sw_) + sqrtf(Se_);
        float sim_p = Sim + sqrtf(g_ent[0]) * g_ent[1];
        out[0] = recon + lamb[0] * param + sim_p;
    }
}

// ---------------------------------------------------------------------------
// Launch
// Inputs (metadata order):
//  0 actual (NE*NW f32)   1 prediction (NE*NW f32)
//  2 W (KD*NW f32)        3 E (NE*KD f32)
//  4 Sw (NW*NW f32)       5 Se (NE*NE f32)
//  6 lamb (1 f32)         7 row_ind (1 i32)
//  8 word_i_indices (GG*MM i32)
//  9 entity_j_indices (JJ i32)
// 10 sample_j_indices (GG i32)
// ---------------------------------------------------------------------------
extern "C" void kernel_launch(void* const* d_in, const int* in_sizes, int n_in,
                              void* d_out, int out_size) {
    const float* actual = (const float*)d_in[0];
    const float* pred   = (const float*)d_in[1];
    const float* W      = (const float*)d_in[2];
    const float* E      = (const float*)d_in[3];
    const float* Sw     = (const float*)d_in[4];
    const float* Se     = (const float*)d_in[5];
    const float* lamb   = (const float*)d_in[6];
    const int*   rowi   = (const int*)  d_in[7];
    const int*   wi     = (const int*)  d_in[8];
    const int*   ej     = (const int*)  d_in[9];
    const int*   sj     = (const int*)  d_in[10];
    float* out = (float*)d_out;

    transpose_k<<<dim3(NW / 32, KD / 32), dim3(32, 8)>>>(W);
    gather_k<<<GG, 128>>>(Sw, wi, sj);
    entity_k<<<1, 1024>>>(E, Se, ej, rowi);
    big_reduce_k<<<NBLK, NTHR>>>(actual, pred, W, E);
    final_k<<<1, 256>>>(lamb, out);
}

// round 2
// speedup vs baseline: 1.2562x; 1.2562x over previous
#include <cuda_runtime.h>
#include <math.h>

// Problem constants (fixed by the dataset)
#define NE 4096
#define NW 8192
#define KD 128
#define GG 1024
#define MM 64
#define JJ 256

#define NBLK 1184   // 148 SMs * 8 blocks
#define NTHR 256

// Scratch (device globals — no runtime allocation allowed)
__device__ float g_Wt[NW * KD];          // transposed W (4 MB)
__device__ float g_pr[NBLK];
__device__ float g_pw[NBLK];
__device__ float g_pe[NBLK];
__device__ float g_sim[GG];
__device__ float g_ent[2];

__device__ __forceinline__ float block_reduce(float v) {
    __shared__ float sh[32];
    int lane = threadIdx.x & 31;
    int wid  = threadIdx.x >> 5;
    #pragma unroll
    for (int o = 16; o > 0; o >>= 1) v += __shfl_down_sync(0xffffffffu, v, o);
    __syncthreads();
    if (lane == 0) sh[wid] = v;
    __syncthreads();
    int nwarps = (blockDim.x + 31) >> 5;
    v = (threadIdx.x < nwarps) ? sh[threadIdx.x] : 0.0f;
    if (wid == 0) {
        #pragma unroll
        for (int o = 16; o > 0; o >>= 1) v += __shfl_down_sync(0xffffffffu, v, o);
    }
    return v;   // valid in thread 0
}

// ---------------------------------------------------------------------------
// 1) Transpose W (KD x NW) -> g_Wt (NW x KD)
// ---------------------------------------------------------------------------
__global__ void transpose_k(const float* __restrict__ W) {
    __shared__ float tile[32][33];
    int n = blockIdx.x * 32 + threadIdx.x;
    int k = blockIdx.y * 32 + threadIdx.y;
    #pragma unroll
    for (int i = 0; i < 32; i += 8)
        tile[threadIdx.y + i][threadIdx.x] = W[(size_t)(k + i) * NW + n];
    __syncthreads();
    int ko = blockIdx.y * 32 + threadIdx.x;
    int no = blockIdx.x * 32 + threadIdx.y;
    #pragma unroll
    for (int i = 0; i < 32; i += 8)
        g_Wt[(size_t)(no + i) * KD + ko] = tile[threadIdx.x][threadIdx.y + i];
}

// ---------------------------------------------------------------------------
// 2) Big HBM-bound reduce with deep MLP: 8 independent float4 loads in flight
// ---------------------------------------------------------------------------
__global__ void __launch_bounds__(NTHR) big_reduce_k(const float* __restrict__ a,
                             const float* __restrict__ p,
                             const float* __restrict__ W,
                             const float* __restrict__ E) {
    const int tid    = blockIdx.x * blockDim.x + threadIdx.x;
    const int stride = gridDim.x * blockDim.x;

    const float4* a4 = (const float4*)a;
    const float4* p4 = (const float4*)p;
    const int n4 = (NE * NW) / 4;     // 8M

    float s0 = 0.f, s1 = 0.f, s2 = 0.f, s3 = 0.f;
    int i = tid;
    for (; i + 3 * stride < n4; i += 4 * stride) {
        float4 av0 = a4[i];
        float4 av1 = a4[i +     stride];
        float4 av2 = a4[i + 2 * stride];
        float4 av3 = a4[i + 3 * stride];
        float4 pv0 = p4[i];
        float4 pv1 = p4[i +     stride];
        float4 pv2 = p4[i + 2 * stride];
        float4 pv3 = p4[i + 3 * stride];
        float d;
        d = av0.x - pv0.x; s0 += d * d; d = av0.y - pv0.y; s0 += d * d;
        d = av0.z - pv0.z; s0 += d * d; d = av0.w - pv0.w; s0 += d * d;
        d = av1.x - pv1.x; s1 += d * d; d = av1.y - pv1.y; s1 += d * d;
        d = av1.z - pv1.z; s1 += d * d; d = av1.w - pv1.w; s1 += d * d;
        d = av2.x - pv2.x; s2 += d * d; d = av2.y - pv2.y; s2 += d * d;
        d = av2.z - pv2.z; s2 += d * d; d = av2.w - pv2.w; s2 += d * d;
        d = av3.x - pv3.x; s3 += d * d; d = av3.y - pv3.y; s3 += d * d;
        d = av3.z - pv3.z; s3 += d * d; d = av3.w - pv3.w; s3 += d * d;
    }
    for (; i < n4; i += stride) {
        float4 av = a4[i];
        float4 pv = p4[i];
        float d;
        d = av.x - pv.x; s0 += d * d; d = av.y - pv.y; s0 += d * d;
        d = av.z - pv.z; s0 += d * d; d = av.w - pv.w; s0 += d * d;
    }
    float s_r = (s0 + s1) + (s2 + s3);

    float s_w = 0.0f;
    const float4* w4 = (const float4*)W;
    const int nw4 = (KD * NW) / 4;    // 256K
    for (int q = tid; q < nw4; q += stride) {
        float4 v = w4[q];
        float r0 = fmaxf(v.x, 0.f), r1 = fmaxf(v.y, 0.f);
        float r2 = fmaxf(v.z, 0.f), r3 = fmaxf(v.w, 0.f);
        s_w += r0 * r0 + r1 * r1 + r2 * r2 + r3 * r3;
    }

    float s_e = 0.0f;
    const float4* e4 = (const float4*)E;
    const int ne4 = (NE * KD) / 4;    // 128K
    for (int q = tid; q < ne4; q += stride) {
        float4 v = e4[q];
        float r0 = fmaxf(v.x, 0.f), r1 = fmaxf(v.y, 0.f);
        float r2 = fmaxf(v.z, 0.f), r3 = fmaxf(v.w, 0.f);
        s_e += r0 * r0 + r1 * r1 + r2 * r2 + r3 * r3;
    }

    float br = block_reduce(s_r);
    __syncthreads();
    float bw = block_reduce(s_w);
    __syncthreads();
    float be = block_reduce(s_e);
    if (threadIdx.x == 0) {
        g_pr[blockIdx.x] = br;
        g_pw[blockIdx.x] = bw;
        g_pe[blockIdx.x] = be;
    }
}

// ---------------------------------------------------------------------------
// 3) Word-gather kernel: block per g, 128 threads = K dim
// ---------------------------------------------------------------------------
__global__ void gather_k(const float* __restrict__ Sw,
                         const int*   __restrict__ wi,
                         const int*   __restrict__ sj) {
    const int g = blockIdx.x;
    const int k = threadIdx.x;            // 0..127

    __shared__ int idxs[MM];
    const int j = sj[g];
    if (k < MM) idxs[k] = wi[g * MM + k];
    __syncthreads();

    const float wjk = g_Wt[(size_t)j * KD + k];

    float acc = 0.0f;
    #pragma unroll 4
    for (int m = 0; m < MM; m++) {
        float d = wjk - g_Wt[(size_t)idxs[m] * KD + k];
        acc += d * d;
    }

    float swv = 0.0f;
    if (k < MM) swv = Sw[(size_t)j * NW + idxs[k]];

    float d2 = block_reduce(acc);
    __syncthreads();
    float sw = block_reduce(swv);
    if (k == 0) g_sim[g] = sqrtf(d2) * sw;
}

// ---------------------------------------------------------------------------
// 4) Entity kernel: 1 block x 1024 threads
// ---------------------------------------------------------------------------
__global__ void entity_k(const float* __restrict__ E,
                         const float* __restrict__ Se,
                         const int*   __restrict__ ej,
                         const int*   __restrict__ row_ind_p) {
    const int row = row_ind_p[0];
    const int t = threadIdx.x;

    __shared__ float erow[KD];
    __shared__ int   ejs[JJ];
    if (t < KD) erow[t] = E[(size_t)row * KD + t];
    if (t < JJ) ejs[t] = ej[t];
    __syncthreads();

    float s_de = 0.0f;
    #pragma unroll 4
    for (int i = t; i < JJ * KD; i += 1024) {
        int jj = i >> 7;
        int kk = i & (KD - 1);
        float d = erow[kk] - E[(size_t)ejs[jj] * KD + kk];
        s_de += d * d;
    }

    float s_se = 0.0f;
    if (t < JJ) s_se = Se[(size_t)row * NE + ejs[t]];

    float de = block_reduce(s_de);
    __syncthreads();
    float se = block_reduce(s_se);
    if (t == 0) { g_ent[0] = de; g_ent[1] = se; }
}

// ---------------------------------------------------------------------------
// 5) Final compose
// ---------------------------------------------------------------------------
__global__ void final_k(const float* __restrict__ lamb, float* __restrict__ out) {
    const int t = threadIdx.x;
    float sr = 0.f, sw = 0.f, se = 0.f, sim = 0.f;
    for (int i = t; i < NBLK; i += 256) {
        sr += g_pr[i];
        sw += g_pw[i];
        se += g_pe[i];
    }
    for (int i = t; i < GG; i += 256) sim += g_sim[i];

    float Sr  = block_reduce(sr);   __syncthreads();
    float Sw_ = block_reduce(sw);   __syncthreads();
    float Se_ = block_reduce(se);   __syncthreads();
    float Sim = block_reduce(sim);

    if (t == 0) {
        float recon = sqrtf(Sr);
        float param = sqrtf(Sw_) + sqrtf(Se_);
        float sim_p = Sim + sqrtf(g_ent[0]) * g_ent[1];
        out[0] = recon + lamb[0] * param + sim_p;
    }
}

// ---------------------------------------------------------------------------
// Launch: fork/join streams so the small chain overlaps the HBM-bound reduce.
// Streams & events are created once (before any graph capture — the harness's
// correctness call precedes capture) and reused; behavior per call is constant.
// ---------------------------------------------------------------------------
static cudaStream_t g_s1 = (cudaStream_t)0;
static cudaEvent_t  g_evFork = (cudaEvent_t)0;
static cudaEvent_t  g_evJoin = (cudaEvent_t)0;

extern "C" void kernel_launch(void* const* d_in, const int* in_sizes, int n_in,
                              void* d_out, int out_size) {
    const float* actual = (const float*)d_in[0];
    const float* pred   = (const float*)d_in[1];
    const float* W      = (const float*)d_in[2];
    const float* E      = (const float*)d_in[3];
    const float* Sw     = (const float*)d_in[4];
    const float* Se     = (const float*)d_in[5];
    const float* lamb   = (const float*)d_in[6];
    const int*   rowi   = (const int*)  d_in[7];
    const int*   wi     = (const int*)  d_in[8];
    const int*   ej     = (const int*)  d_in[9];
    const int*   sj     = (const int*)  d_in[10];
    float* out = (float*)d_out;

    if (g_s1 == (cudaStream_t)0) {
        cudaStreamCreateWithFlags(&g_s1, cudaStreamNonBlocking);
        cudaEventCreateWithFlags(&g_evFork, cudaEventDisableTiming);
        cudaEventCreateWithFlags(&g_evJoin, cudaEventDisableTiming);
    }

    // Fork: side stream gets a dependency on everything prior on stream 0.
    cudaEventRecord(g_evFork, 0);
    cudaStreamWaitEvent(g_s1, g_evFork, 0);

    // Side stream: transpose -> gather -> entity (all small, mostly L2).
    transpose_k<<<dim3(NW / 32, KD / 32), dim3(32, 8), 0, g_s1>>>(W);
    gather_k<<<GG, 128, 0, g_s1>>>(Sw, wi, sj);
    entity_k<<<1, 1024, 0, g_s1>>>(E, Se, ej, rowi);
    cudaEventRecord(g_evJoin, g_s1);

    // Main stream: the HBM-roofline kernel runs concurrently.
    big_reduce_k<<<NBLK, NTHR>>>(actual, pred, W, E);

    // Join, then compose the scalar.
    cudaStreamWaitEvent((cudaStream_t)0, g_evJoin, 0);
    final_k<<<1, 256>>>(lamb, out);
}